// round 1
// baseline (speedup 1.0000x reference)
#include <cuda_runtime.h>
#include <math.h>

#define NN 50000
#define DF 128
#define HEADS 4
#define MAXE 800000

// ---------------- scratch (device globals; no allocations) ----------------
__device__ float g_agg[NN * DF];          // SAGE neighbor sum; later reused as GAT node output "g"
__device__ float g_cnt[NN];
__device__ float g_h[NN * DF];            // SAGE output
__device__ float g_hs[NN * HEADS * DF];   // h @ W_src  [N, 4, 128]
__device__ float g_as[NN * HEADS];
__device__ float g_ad[NN * HEADS];
__device__ float g_m[NN * HEADS];         // segment max
__device__ float g_den[NN * HEADS];       // segment sum of exp
__device__ float g_accum[NN * HEADS * DF];// unnormalized GAT aggregation
__device__ float g_eexp[MAXE * HEADS];
__device__ float g_vs[DF * HEADS];
__device__ float g_vd[DF * HEADS];

// ---------------- utility kernels ----------------
__global__ void k_zero4(float* p, int n4) {
    int i = blockIdx.x * blockDim.x + threadIdx.x;
    if (i < n4) ((float4*)p)[i] = make_float4(0.f, 0.f, 0.f, 0.f);
}
__global__ void k_fill(float* p, int n, float v) {
    int i = blockIdx.x * blockDim.x + threadIdx.x;
    if (i < n) p[i] = v;
}

// ---------------- SAGE scatter: warp per edge ----------------
__global__ void k_sage_scatter(const float* __restrict__ x, const int* __restrict__ ei, int E) {
    int gt = blockIdx.x * blockDim.x + threadIdx.x;
    int e = gt >> 5;
    int lane = gt & 31;
    if (e >= E) return;
    int s = ei[e];
    int d = ei[E + e];
    float4 v = ((const float4*)(x + (size_t)s * DF))[lane];
    float* ar = g_agg + (size_t)d * DF + lane * 4;
    atomicAdd(ar + 0, v.x);
    atomicAdd(ar + 1, v.y);
    atomicAdd(ar + 2, v.z);
    atomicAdd(ar + 3, v.w);
    if (lane == 0) atomicAdd(&g_cnt[d], 1.0f);
}

__global__ void k_mean(int n) {  // agg /= max(cnt,1)
    int i = blockIdx.x * blockDim.x + threadIdx.x;
    if (i < n) {
        float c = g_cnt[i >> 7];
        g_agg[i] = g_agg[i] / fmaxf(c, 1.0f);
    }
}

// ---------------- generic tiled GEMM, K = 128 fixed ----------------
// C[M, Ncols] = A[M,128] @ B[128, Ncols]  (+ C if accumulate) (+ bias) (relu)
#define BM 64
#define BN 64
#define BK 64
__global__ void k_gemm(const float* __restrict__ A, const float* __restrict__ B,
                       const float* __restrict__ bias, float* __restrict__ C,
                       int M, int Ncols, int accumulate, int do_relu) {
    __shared__ float As[BM][BK + 4];
    __shared__ float Bs[BK][BN + 4];
    int tid = threadIdx.x;              // 256 threads
    int tx = tid & 15, ty = tid >> 4;   // 16 x 16
    int m0 = blockIdx.x * BM, n0 = blockIdx.y * BN;
    float acc[4][4] = {};

    for (int k0 = 0; k0 < 128; k0 += BK) {
        // load A tile 64x64
        #pragma unroll
        for (int r = 0; r < BM; r += 16) {
            int row = r + (tid >> 4);
            int col = (tid & 15) * 4;
            float4 v = make_float4(0.f, 0.f, 0.f, 0.f);
            if (m0 + row < M)
                v = *(const float4*)(A + (size_t)(m0 + row) * 128 + k0 + col);
            As[row][col] = v.x; As[row][col + 1] = v.y;
            As[row][col + 2] = v.z; As[row][col + 3] = v.w;
        }
        // load B tile 64x64
        #pragma unroll
        for (int r = 0; r < BK; r += 16) {
            int row = r + (tid >> 4);
            int col = (tid & 15) * 4;
            float4 v = *(const float4*)(B + (size_t)(k0 + row) * Ncols + n0 + col);
            Bs[row][col] = v.x; Bs[row][col + 1] = v.y;
            Bs[row][col + 2] = v.z; Bs[row][col + 3] = v.w;
        }
        __syncthreads();
        #pragma unroll 16
        for (int kk = 0; kk < BK; kk++) {
            float a[4], b[4];
            #pragma unroll
            for (int i = 0; i < 4; i++) a[i] = As[ty * 4 + i][kk];
            #pragma unroll
            for (int j = 0; j < 4; j++) b[j] = Bs[kk][tx * 4 + j];
            #pragma unroll
            for (int i = 0; i < 4; i++)
                #pragma unroll
                for (int j = 0; j < 4; j++)
                    acc[i][j] = fmaf(a[i], b[j], acc[i][j]);
        }
        __syncthreads();
    }
    #pragma unroll
    for (int i = 0; i < 4; i++) {
        int row = m0 + ty * 4 + i;
        if (row >= M) continue;
        #pragma unroll
        for (int j = 0; j < 4; j++) {
            int col = n0 + tx * 4 + j;
            float v = acc[i][j];
            size_t idx = (size_t)row * Ncols + col;
            if (accumulate) v += C[idx];
            if (bias) v += bias[col];
            if (do_relu) v = fmaxf(v, 0.f);
            C[idx] = v;
        }
    }
}

// ---------------- attention-vector precompute ----------------
// v_s[k,h] = sum_c W_src[k, h*128+c] * att_src[h,c]   (same for dst)
__global__ void k_att_vec(const float* __restrict__ Wsrc, const float* __restrict__ Wdst,
                          const float* __restrict__ atts, const float* __restrict__ attd) {
    int t = blockIdx.x * blockDim.x + threadIdx.x;
    if (t >= DF * HEADS) return;
    int k = t >> 2, h = t & 3;
    float s = 0.f, d = 0.f;
    for (int c = 0; c < DF; c++) {
        s = fmaf(Wsrc[(size_t)k * 512 + h * 128 + c], atts[h * 128 + c], s);
        d = fmaf(Wdst[(size_t)k * 512 + h * 128 + c], attd[h * 128 + c], d);
    }
    g_vs[k * 4 + h] = s;
    g_vd[k * 4 + h] = d;
}

// ---------------- per-node a_s, a_d: warp per node ----------------
__global__ void k_asd(int N) {
    __shared__ float svs[DF * 4], svd[DF * 4];
    for (int i = threadIdx.x; i < DF * 4; i += blockDim.x) {
        svs[i] = g_vs[i];
        svd[i] = g_vd[i];
    }
    __syncthreads();
    int gt = blockIdx.x * blockDim.x + threadIdx.x;
    int n = gt >> 5, lane = gt & 31;
    if (n >= N) return;
    float as[4] = {}, ad[4] = {};
    #pragma unroll
    for (int kk = 0; kk < 4; kk++) {
        int k = lane + kk * 32;
        float hv = g_h[(size_t)n * DF + k];
        #pragma unroll
        for (int h = 0; h < 4; h++) {
            as[h] = fmaf(hv, svs[k * 4 + h], as[h]);
            ad[h] = fmaf(hv, svd[k * 4 + h], ad[h]);
        }
    }
    #pragma unroll
    for (int h = 0; h < 4; h++) {
        #pragma unroll
        for (int off = 16; off > 0; off >>= 1) {
            as[h] += __shfl_down_sync(0xffffffff, as[h], off);
            ad[h] += __shfl_down_sync(0xffffffff, ad[h], off);
        }
    }
    if (lane == 0) {
        #pragma unroll
        for (int h = 0; h < 4; h++) {
            g_as[n * 4 + h] = as[h];
            g_ad[n * 4 + h] = ad[h];
        }
    }
}

__device__ __forceinline__ float lrelu(float v) { return v > 0.f ? v : 0.2f * v; }

__device__ __forceinline__ void atomicMaxF(float* addr, float val) {
    if (val >= 0.f)
        atomicMax((int*)addr, __float_as_int(val));
    else
        atomicMin((unsigned int*)addr, __float_as_uint(val));
}

// ---------------- edge pass A: segment max ----------------
__global__ void k_edge_max(const int* __restrict__ ei, int E) {
    int e = blockIdx.x * blockDim.x + threadIdx.x;
    if (e >= E) return;
    int s = ei[e], d = ei[E + e];
    float4 as = *(const float4*)(g_as + s * 4);
    float4 ad = *(const float4*)(g_ad + d * 4);
    atomicMaxF(&g_m[d * 4 + 0], lrelu(as.x + ad.x));
    atomicMaxF(&g_m[d * 4 + 1], lrelu(as.y + ad.y));
    atomicMaxF(&g_m[d * 4 + 2], lrelu(as.z + ad.z));
    atomicMaxF(&g_m[d * 4 + 3], lrelu(as.w + ad.w));
}

// ---------------- edge pass B: exp + denom ----------------
__global__ void k_edge_exp(const int* __restrict__ ei, int E) {
    int e = blockIdx.x * blockDim.x + threadIdx.x;
    if (e >= E) return;
    int s = ei[e], d = ei[E + e];
    float4 as = *(const float4*)(g_as + s * 4);
    float4 ad = *(const float4*)(g_ad + d * 4);
    float4 mm = *(const float4*)(g_m + d * 4);
    float x0 = expf(lrelu(as.x + ad.x) - mm.x);
    float x1 = expf(lrelu(as.y + ad.y) - mm.y);
    float x2 = expf(lrelu(as.z + ad.z) - mm.z);
    float x3 = expf(lrelu(as.w + ad.w) - mm.w);
    *(float4*)(g_eexp + (size_t)e * 4) = make_float4(x0, x1, x2, x3);
    atomicAdd(&g_den[d * 4 + 0], x0);
    atomicAdd(&g_den[d * 4 + 1], x1);
    atomicAdd(&g_den[d * 4 + 2], x2);
    atomicAdd(&g_den[d * 4 + 3], x3);
}

// ---------------- edge pass C: messages (warp per edge) ----------------
__global__ void k_edge_msg(const int* __restrict__ ei, int E) {
    int gt = blockIdx.x * blockDim.x + threadIdx.x;
    int e = gt >> 5, lane = gt & 31;
    if (e >= E) return;
    int s = ei[e], d = ei[E + e];
    float4 w4 = *(const float4*)(g_eexp + (size_t)e * 4);
    float wh[4] = {w4.x, w4.y, w4.z, w4.w};
    const float4* hsrc = (const float4*)(g_hs + (size_t)s * 512);
    float* adst = g_accum + (size_t)d * 512;
    #pragma unroll
    for (int h = 0; h < 4; h++) {
        float4 v = hsrc[h * 32 + lane];
        float w = wh[h];
        float* p = adst + h * 128 + lane * 4;
        atomicAdd(p + 0, v.x * w);
        atomicAdd(p + 1, v.y * w);
        atomicAdd(p + 2, v.z * w);
        atomicAdd(p + 3, v.w * w);
    }
}

// ---------------- GAT node epilogue: g = relu(mean_h(accum/den) + b) ----------------
__global__ void k_gat_epi(const float* __restrict__ b_gat, int N) {
    int i = blockIdx.x * blockDim.x + threadIdx.x;
    if (i >= N * DF) return;
    int n = i >> 7, c = i & 127;
    float4 den = *(const float4*)(g_den + n * 4);
    float i0 = den.x > 0.f ? 1.f / den.x : 0.f;
    float i1 = den.y > 0.f ? 1.f / den.y : 0.f;
    float i2 = den.z > 0.f ? 1.f / den.z : 0.f;
    float i3 = den.w > 0.f ? 1.f / den.w : 0.f;
    const float* a = g_accum + (size_t)n * 512;
    float v = a[c] * i0 + a[128 + c] * i1 + a[256 + c] * i2 + a[384 + c] * i3;
    v = 0.25f * v + b_gat[c];
    g_agg[i] = fmaxf(v, 0.f);   // reuse g_agg as the GAT output buffer
}

// ---------------- launch ----------------
extern "C" void kernel_launch(void* const* d_in, const int* in_sizes, int n_in,
                              void* d_out, int out_size) {
    const float* x      = (const float*)d_in[0];
    const int*   ei     = (const int*)d_in[1];
    const float* W_l    = (const float*)d_in[2];
    const float* W_r    = (const float*)d_in[3];
    const float* b_sage = (const float*)d_in[4];
    const float* W_src  = (const float*)d_in[5];
    const float* W_dst  = (const float*)d_in[6];
    const float* att_s  = (const float*)d_in[7];
    const float* att_d  = (const float*)d_in[8];
    const float* b_gat  = (const float*)d_in[9];
    const float* W_lin  = (const float*)d_in[10];
    const float* b_lin  = (const float*)d_in[11];
    float* out = (float*)d_out;

    int N = in_sizes[0] / DF;
    int E = in_sizes[1] / 2;

    float *p_agg, *p_cnt, *p_h, *p_hs, *p_m, *p_den, *p_accum;
    cudaGetSymbolAddress((void**)&p_agg, g_agg);
    cudaGetSymbolAddress((void**)&p_cnt, g_cnt);
    cudaGetSymbolAddress((void**)&p_h, g_h);
    cudaGetSymbolAddress((void**)&p_hs, g_hs);
    cudaGetSymbolAddress((void**)&p_m, g_m);
    cudaGetSymbolAddress((void**)&p_den, g_den);
    cudaGetSymbolAddress((void**)&p_accum, g_accum);

    const int T = 256;
    // ---- init scratch ----
    k_zero4<<<(N * DF / 4 + T - 1) / T, T>>>(p_agg, N * DF / 4);
    k_fill<<<(N + T - 1) / T, T>>>(p_cnt, N, 0.f);
    k_fill<<<(N * HEADS + T - 1) / T, T>>>(p_m, N * HEADS, -INFINITY);
    k_zero4<<<(N * HEADS / 4 + T - 1) / T, T>>>(p_den, N * HEADS / 4);
    k_zero4<<<(N * 512 / 4 + T - 1) / T, T>>>(p_accum, N * 512 / 4);

    // ---- SAGE ----
    int warpBlocks = (E * 32 + T - 1) / T;
    k_sage_scatter<<<warpBlocks, T>>>(x, ei, E);
    k_mean<<<(N * DF + T - 1) / T, T>>>(N * DF);

    dim3 g1((N + BM - 1) / BM, DF / BN);
    k_gemm<<<g1, 256>>>(p_agg, W_l, nullptr, p_h, N, DF, 0, 0);        // h  = mean @ W_l
    k_gemm<<<g1, 256>>>(x, W_r, b_sage, p_h, N, DF, 1, 1);             // h += x @ W_r + b, relu

    // ---- GAT ----
    dim3 g2((N + BM - 1) / BM, (HEADS * DF) / BN);
    k_gemm<<<g2, 256>>>(p_h, W_src, nullptr, p_hs, N, HEADS * DF, 0, 0);  // hs = h @ W_src

    k_att_vec<<<2, 256>>>(W_src, W_dst, att_s, att_d);
    k_asd<<<(N * 32 + T - 1) / T, T>>>(N);

    int edgeBlocks = (E + T - 1) / T;
    k_edge_max<<<edgeBlocks, T>>>(ei, E);
    k_edge_exp<<<edgeBlocks, T>>>(ei, E);
    k_edge_msg<<<warpBlocks, T>>>(ei, E);

    k_gat_epi<<<(N * DF + T - 1) / T, T>>>(b_gat, N);

    // ---- final linear ----
    dim3 g3((N + BM - 1) / BM, 64 / BN);
    k_gemm<<<g3, 256>>>(p_agg, W_lin, b_lin, out, N, 64, 0, 0);
}

// round 2
// speedup vs baseline: 2.7385x; 2.7385x over previous
#include <cuda_runtime.h>
#include <math.h>

#define NN 50000
#define DF 128
#define HEADS 4
#define MAXE 800000

// ---------------- scratch (device globals; no allocations) ----------------
__device__ float g_agg[NN * DF];            // SAGE mean; later reused as GAT node output "g"
__device__ float g_h[NN * DF];              // SAGE output
__device__ float g_aggh[NN * HEADS * DF];   // GAT per-head aggregated h
__device__ float g_as[NN * HEADS];
__device__ float g_ad[NN * HEADS];
__device__ float g_vs[DF * HEADS];
__device__ float g_vd[DF * HEADS];
__device__ float g_bstack[HEADS * DF * DF]; // rearranged 0.25*W_src  [512,128]
__device__ int   g_deg[NN];
__device__ int   g_rowptr[NN + 1];
__device__ int   g_cursor[NN];
__device__ int   g_csrsrc[MAXE];

__device__ __forceinline__ float lrelu(float v) { return v > 0.f ? v : 0.2f * v; }

// ---------------- CSR build ----------------
__global__ void k_zero_int(int* p, int n) {
    int i = blockIdx.x * blockDim.x + threadIdx.x;
    if (i < n) p[i] = 0;
}
__global__ void k_count(const int* __restrict__ ei, int E) {
    int e = blockIdx.x * blockDim.x + threadIdx.x;
    if (e < E) atomicAdd(&g_deg[ei[E + e]], 1);
}
// single block 1024 threads: exclusive scan of g_deg -> g_rowptr, zero cursor
__global__ void k_scan(int N) {
    __shared__ int warpsums[32];
    int tid = threadIdx.x;
    int CH = (N + 1023) >> 10;
    int base = tid * CH;
    int s = 0;
    for (int i = 0; i < CH; i++) {
        int idx = base + i;
        if (idx < N) s += g_deg[idx];
    }
    int lane = tid & 31, wid = tid >> 5;
    int v = s;
    #pragma unroll
    for (int o = 1; o < 32; o <<= 1) {
        int t = __shfl_up_sync(0xffffffff, v, o);
        if (lane >= o) v += t;
    }
    if (lane == 31) warpsums[wid] = v;
    __syncthreads();
    if (wid == 0) {
        int w = warpsums[lane];
        #pragma unroll
        for (int o = 1; o < 32; o <<= 1) {
            int t = __shfl_up_sync(0xffffffff, w, o);
            if (lane >= o) w += t;
        }
        warpsums[lane] = w;
    }
    __syncthreads();
    int offset = v - s + (wid > 0 ? warpsums[wid - 1] : 0);
    for (int i = 0; i < CH; i++) {
        int idx = base + i;
        if (idx < N) {
            g_rowptr[idx] = offset;
            offset += g_deg[idx];
            g_cursor[idx] = 0;
        }
    }
    if (tid == 1023) g_rowptr[N] = offset;
}
__global__ void k_csr_scatter(const int* __restrict__ ei, int E) {
    int e = blockIdx.x * blockDim.x + threadIdx.x;
    if (e >= E) return;
    int s = ei[e], d = ei[E + e];
    int pos = atomicAdd(&g_cursor[d], 1);
    g_csrsrc[g_rowptr[d] + pos] = s;
}

// ---------------- SAGE mean gather: warp per node ----------------
__global__ void k_sage_gather(const float* __restrict__ x, int N) {
    int gt = blockIdx.x * blockDim.x + threadIdx.x;
    int n = gt >> 5, lane = gt & 31;
    if (n >= N) return;
    int beg = g_rowptr[n], end = g_rowptr[n + 1];
    float4 acc = make_float4(0.f, 0.f, 0.f, 0.f);
    for (int i = beg; i < end; i++) {
        int s = g_csrsrc[i];
        float4 v = ((const float4*)(x + (size_t)s * DF))[lane];
        acc.x += v.x; acc.y += v.y; acc.z += v.z; acc.w += v.w;
    }
    float inv = 1.f / fmaxf((float)(end - beg), 1.f);
    acc.x *= inv; acc.y *= inv; acc.z *= inv; acc.w *= inv;
    ((float4*)(g_agg + (size_t)n * DF))[lane] = acc;
}

// ---------------- SGEMM: C = A1@B1 (+A2@B2) (+bias) (relu) ----------------
#define BM 128
#define BN 64
#define BK 32
__global__ void k_gemm(const float* __restrict__ A1, const float* __restrict__ B1,
                       const float* __restrict__ A2, const float* __restrict__ B2,
                       const float* __restrict__ bias, float* __restrict__ C,
                       int M, int K, int Ncols, int do_relu) {
    __shared__ float As[BK][BM + 4];   // transposed A tile
    __shared__ float Bs[BK][BN + 4];
    int tid = threadIdx.x;             // 256 threads
    int tx = tid & 15, ty = tid >> 4;  // 16 x 16
    int m0 = blockIdx.x * BM, n0 = blockIdx.y * BN;
    float acc[8][4] = {};
    int npairs = A2 ? 2 : 1;

    for (int p = 0; p < npairs; p++) {
        const float* A = p ? A2 : A1;
        const float* B = p ? B2 : B1;
        for (int k0 = 0; k0 < K; k0 += BK) {
            // A tile: BM x BK = 1024 float4; 4 per thread; store transposed
            #pragma unroll
            for (int i = 0; i < 4; i++) {
                int fid = tid * 4 + i;
                int row = fid >> 3;
                int c4 = fid & 7;
                float4 v = make_float4(0.f, 0.f, 0.f, 0.f);
                if (m0 + row < M)
                    v = *(const float4*)(A + (size_t)(m0 + row) * K + k0 + c4 * 4);
                As[c4 * 4 + 0][row] = v.x;
                As[c4 * 4 + 1][row] = v.y;
                As[c4 * 4 + 2][row] = v.z;
                As[c4 * 4 + 3][row] = v.w;
            }
            // B tile: BK x BN = 512 float4; 2 per thread
            #pragma unroll
            for (int i = 0; i < 2; i++) {
                int fid = tid * 2 + i;
                int row = fid >> 4;
                int c4 = fid & 15;
                float4 v = *(const float4*)(B + (size_t)(k0 + row) * Ncols + n0 + c4 * 4);
                *(float4*)&Bs[row][c4 * 4] = v;
            }
            __syncthreads();
            #pragma unroll
            for (int kk = 0; kk < BK; kk++) {
                float4 a0 = *(const float4*)&As[kk][ty * 8];
                float4 a1 = *(const float4*)&As[kk][ty * 8 + 4];
                float4 b = *(const float4*)&Bs[kk][tx * 4];
                float av[8] = {a0.x, a0.y, a0.z, a0.w, a1.x, a1.y, a1.z, a1.w};
                float bv[4] = {b.x, b.y, b.z, b.w};
                #pragma unroll
                for (int i = 0; i < 8; i++)
                    #pragma unroll
                    for (int j = 0; j < 4; j++)
                        acc[i][j] = fmaf(av[i], bv[j], acc[i][j]);
            }
            __syncthreads();
        }
    }
    #pragma unroll
    for (int i = 0; i < 8; i++) {
        int row = m0 + ty * 8 + i;
        if (row >= M) continue;
        int col = n0 + tx * 4;
        float4 o = make_float4(acc[i][0], acc[i][1], acc[i][2], acc[i][3]);
        if (bias) {
            o.x += bias[col]; o.y += bias[col + 1];
            o.z += bias[col + 2]; o.w += bias[col + 3];
        }
        if (do_relu) {
            o.x = fmaxf(o.x, 0.f); o.y = fmaxf(o.y, 0.f);
            o.z = fmaxf(o.z, 0.f); o.w = fmaxf(o.w, 0.f);
        }
        *(float4*)(C + (size_t)row * Ncols + col) = o;
    }
}

// ---------------- attention-vector precompute ----------------
__global__ void k_att_vec(const float* __restrict__ Wsrc, const float* __restrict__ Wdst,
                          const float* __restrict__ atts, const float* __restrict__ attd) {
    int t = blockIdx.x * blockDim.x + threadIdx.x;
    if (t >= DF * HEADS) return;
    int k = t >> 2, h = t & 3;
    float s = 0.f, d = 0.f;
    for (int c = 0; c < DF; c++) {
        s = fmaf(Wsrc[(size_t)k * 512 + h * 128 + c], atts[h * 128 + c], s);
        d = fmaf(Wdst[(size_t)k * 512 + h * 128 + c], attd[h * 128 + c], d);
    }
    g_vs[k * 4 + h] = s;
    g_vd[k * 4 + h] = d;
}

// rearranged stacked GAT weight: Bstack[h*128+k][c] = 0.25 * W_src[k][h*128+c]
__global__ void k_bstack(const float* __restrict__ Wsrc) {
    int t = blockIdx.x * blockDim.x + threadIdx.x;
    if (t >= 512 * 128) return;
    int j = t >> 7, c = t & 127;
    int h = j >> 7, k = j & 127;
    g_bstack[t] = 0.25f * Wsrc[(size_t)k * 512 + h * 128 + c];
}

// ---------------- per-node a_s, a_d: warp per node ----------------
__global__ void k_asd(int N) {
    __shared__ float svs[DF * 4], svd[DF * 4];
    for (int i = threadIdx.x; i < DF * 4; i += blockDim.x) {
        svs[i] = g_vs[i];
        svd[i] = g_vd[i];
    }
    __syncthreads();
    int gt = blockIdx.x * blockDim.x + threadIdx.x;
    int n = gt >> 5, lane = gt & 31;
    if (n >= N) return;
    float as[4] = {}, ad[4] = {};
    #pragma unroll
    for (int kk = 0; kk < 4; kk++) {
        int k = lane + kk * 32;
        float hv = g_h[(size_t)n * DF + k];
        #pragma unroll
        for (int h = 0; h < 4; h++) {
            as[h] = fmaf(hv, svs[k * 4 + h], as[h]);
            ad[h] = fmaf(hv, svd[k * 4 + h], ad[h]);
        }
    }
    #pragma unroll
    for (int h = 0; h < 4; h++) {
        #pragma unroll
        for (int off = 16; off > 0; off >>= 1) {
            as[h] += __shfl_down_sync(0xffffffff, as[h], off);
            ad[h] += __shfl_down_sync(0xffffffff, ad[h], off);
        }
    }
    if (lane == 0) {
        #pragma unroll
        for (int h = 0; h < 4; h++) {
            g_as[n * 4 + h] = as[h];
            g_ad[n * 4 + h] = ad[h];
        }
    }
}

// ---------------- fused GAT softmax + aggregation: warp per node ----------------
// aggh[n,h,:] = sum_e softmax(e)_h * h[src_e,:]   (normalized, deterministic)
__global__ void k_gat_gather(int N) {
    int gt = blockIdx.x * blockDim.x + threadIdx.x;
    int n = gt >> 5, lane = gt & 31;
    if (n >= N) return;
    int beg = g_rowptr[n], end = g_rowptr[n + 1];
    float4 ad = *(const float4*)(g_ad + (size_t)n * 4);

    // pass 1: segment max (lane-parallel over edges)
    float4 m = make_float4(-INFINITY, -INFINITY, -INFINITY, -INFINITY);
    for (int i = beg + lane; i < end; i += 32) {
        int s = g_csrsrc[i];
        float4 as = *(const float4*)(g_as + (size_t)s * 4);
        m.x = fmaxf(m.x, lrelu(as.x + ad.x));
        m.y = fmaxf(m.y, lrelu(as.y + ad.y));
        m.z = fmaxf(m.z, lrelu(as.z + ad.z));
        m.w = fmaxf(m.w, lrelu(as.w + ad.w));
    }
    #pragma unroll
    for (int o = 16; o > 0; o >>= 1) {
        m.x = fmaxf(m.x, __shfl_xor_sync(0xffffffff, m.x, o));
        m.y = fmaxf(m.y, __shfl_xor_sync(0xffffffff, m.y, o));
        m.z = fmaxf(m.z, __shfl_xor_sync(0xffffffff, m.z, o));
        m.w = fmaxf(m.w, __shfl_xor_sync(0xffffffff, m.w, o));
    }

    // pass 2: weighted accumulate (warp-wide per edge; lanes split feature dim)
    float4 den = make_float4(0.f, 0.f, 0.f, 0.f);
    float4 a0 = make_float4(0.f, 0.f, 0.f, 0.f);
    float4 a1 = a0, a2 = a0, a3 = a0;
    for (int i = beg; i < end; i++) {
        int s = g_csrsrc[i];  // broadcast
        float4 as = *(const float4*)(g_as + (size_t)s * 4);
        float4 w;
        w.x = __expf(lrelu(as.x + ad.x) - m.x);
        w.y = __expf(lrelu(as.y + ad.y) - m.y);
        w.z = __expf(lrelu(as.z + ad.z) - m.z);
        w.w = __expf(lrelu(as.w + ad.w) - m.w);
        den.x += w.x; den.y += w.y; den.z += w.z; den.w += w.w;
        float4 hv = ((const float4*)(g_h + (size_t)s * DF))[lane];
        a0.x = fmaf(hv.x, w.x, a0.x); a0.y = fmaf(hv.y, w.x, a0.y);
        a0.z = fmaf(hv.z, w.x, a0.z); a0.w = fmaf(hv.w, w.x, a0.w);
        a1.x = fmaf(hv.x, w.y, a1.x); a1.y = fmaf(hv.y, w.y, a1.y);
        a1.z = fmaf(hv.z, w.y, a1.z); a1.w = fmaf(hv.w, w.y, a1.w);
        a2.x = fmaf(hv.x, w.z, a2.x); a2.y = fmaf(hv.y, w.z, a2.y);
        a2.z = fmaf(hv.z, w.z, a2.z); a2.w = fmaf(hv.w, w.z, a2.w);
        a3.x = fmaf(hv.x, w.w, a3.x); a3.y = fmaf(hv.y, w.w, a3.y);
        a3.z = fmaf(hv.z, w.w, a3.z); a3.w = fmaf(hv.w, w.w, a3.w);
    }
    float i0 = den.x > 0.f ? 1.f / den.x : 0.f;
    float i1 = den.y > 0.f ? 1.f / den.y : 0.f;
    float i2 = den.z > 0.f ? 1.f / den.z : 0.f;
    float i3 = den.w > 0.f ? 1.f / den.w : 0.f;
    float4* outp = (float4*)(g_aggh + (size_t)n * 512);
    a0.x *= i0; a0.y *= i0; a0.z *= i0; a0.w *= i0;
    a1.x *= i1; a1.y *= i1; a1.z *= i1; a1.w *= i1;
    a2.x *= i2; a2.y *= i2; a2.z *= i2; a2.w *= i2;
    a3.x *= i3; a3.y *= i3; a3.z *= i3; a3.w *= i3;
    outp[0 * 32 + lane] = a0;
    outp[1 * 32 + lane] = a1;
    outp[2 * 32 + lane] = a2;
    outp[3 * 32 + lane] = a3;
}

// ---------------- launch ----------------
extern "C" void kernel_launch(void* const* d_in, const int* in_sizes, int n_in,
                              void* d_out, int out_size) {
    const float* x      = (const float*)d_in[0];
    const int*   ei     = (const int*)d_in[1];
    const float* W_l    = (const float*)d_in[2];
    const float* W_r    = (const float*)d_in[3];
    const float* b_sage = (const float*)d_in[4];
    const float* W_src  = (const float*)d_in[5];
    const float* W_dst  = (const float*)d_in[6];
    const float* att_s  = (const float*)d_in[7];
    const float* att_d  = (const float*)d_in[8];
    const float* b_gat  = (const float*)d_in[9];
    const float* W_lin  = (const float*)d_in[10];
    const float* b_lin  = (const float*)d_in[11];
    float* out = (float*)d_out;

    int N = in_sizes[0] / DF;
    int E = in_sizes[1] / 2;

    float *p_agg, *p_h, *p_aggh, *p_bstack;
    int* p_deg;
    cudaGetSymbolAddress((void**)&p_agg, g_agg);
    cudaGetSymbolAddress((void**)&p_h, g_h);
    cudaGetSymbolAddress((void**)&p_aggh, g_aggh);
    cudaGetSymbolAddress((void**)&p_bstack, g_bstack);
    cudaGetSymbolAddress((void**)&p_deg, g_deg);

    const int T = 256;
    int edgeBlocks = (E + T - 1) / T;
    int nodeWarpBlocks = (N * 32 + T - 1) / T;

    // ---- CSR build ----
    k_zero_int<<<(N + T - 1) / T, T>>>(p_deg, N);
    k_count<<<edgeBlocks, T>>>(ei, E);
    k_scan<<<1, 1024>>>(N);
    k_csr_scatter<<<edgeBlocks, T>>>(ei, E);

    // ---- small precomputes (independent) ----
    k_att_vec<<<2, T>>>(W_src, W_dst, att_s, att_d);
    k_bstack<<<(512 * 128 + T - 1) / T, T>>>(W_src);

    // ---- SAGE ----
    k_sage_gather<<<nodeWarpBlocks, T>>>(x, N);
    dim3 g1((N + BM - 1) / BM, DF / BN);
    k_gemm<<<g1, 256>>>(p_agg, W_l, x, W_r, b_sage, p_h, N, 128, DF, 1);  // h = relu(mean@W_l + x@W_r + b)

    // ---- GAT ----
    k_asd<<<nodeWarpBlocks, T>>>(N);
    k_gat_gather<<<nodeWarpBlocks, T>>>(N);
    k_gemm<<<g1, 256>>>(p_aggh, p_bstack, nullptr, nullptr, b_gat, p_agg, N, 512, DF, 1);  // g = relu(aggh@Bstack + b)

    // ---- final linear ----
    dim3 g3((N + BM - 1) / BM, 64 / BN);
    k_gemm<<<g3, 256>>>(p_agg, W_lin, nullptr, nullptr, b_lin, out, N, 128, 64, 0);
}

// round 8
// speedup vs baseline: 2.9074x; 1.0617x over previous
#include <cuda_runtime.h>
#include <cuda_bf16.h>
#include <math.h>
#include <cstdint>

typedef unsigned int u32;

#define NN 50000
#define DF 128
#define HEADS 4
#define MAXE 800000

// ---------------- scratch (device globals; no allocations) ----------------
__device__ float g_agg[NN * DF];            // SAGE mean; later reused as GAT node output
__device__ float g_h[NN * DF];              // SAGE output
__device__ float g_aggh[NN * HEADS * DF];   // GAT per-head aggregated h
__device__ float g_as[NN * HEADS];
__device__ float g_ad[NN * HEADS];
__device__ float g_vs[DF * HEADS];
__device__ float g_vd[DF * HEADS];
__device__ float g_bstack[HEADS * DF * DF]; // rearranged 0.25*W_src  [512,128]
__device__ int   g_deg[NN];
__device__ int   g_rowptr[NN + 1];
__device__ int   g_cursor[NN];
__device__ int   g_csrsrc[MAXE];

__device__ __forceinline__ float lrelu(float v) { return v > 0.f ? v : 0.2f * v; }

// ---------------- CSR build ----------------
__global__ void k_zero_int(int* p, int n) {
    int i = blockIdx.x * blockDim.x + threadIdx.x;
    if (i < n) p[i] = 0;
}
__global__ void k_count(const int* __restrict__ ei, int E) {
    int e = blockIdx.x * blockDim.x + threadIdx.x;
    if (e < E) atomicAdd(&g_deg[ei[E + e]], 1);
}
__global__ void k_scan(int N) {
    __shared__ int warpsums[32];
    int tid = threadIdx.x;
    int CH = (N + 1023) >> 10;
    int base = tid * CH;
    int s = 0;
    for (int i = 0; i < CH; i++) {
        int idx = base + i;
        if (idx < N) s += g_deg[idx];
    }
    int lane = tid & 31, wid = tid >> 5;
    int v = s;
    #pragma unroll
    for (int o = 1; o < 32; o <<= 1) {
        int t = __shfl_up_sync(0xffffffff, v, o);
        if (lane >= o) v += t;
    }
    if (lane == 31) warpsums[wid] = v;
    __syncthreads();
    if (wid == 0) {
        int w = warpsums[lane];
        #pragma unroll
        for (int o = 1; o < 32; o <<= 1) {
            int t = __shfl_up_sync(0xffffffff, w, o);
            if (lane >= o) w += t;
        }
        warpsums[lane] = w;
    }
    __syncthreads();
    int offset = v - s + (wid > 0 ? warpsums[wid - 1] : 0);
    for (int i = 0; i < CH; i++) {
        int idx = base + i;
        if (idx < N) {
            g_rowptr[idx] = offset;
            offset += g_deg[idx];
            g_cursor[idx] = 0;
        }
    }
    if (tid == 1023) g_rowptr[N] = offset;
}
__global__ void k_csr_scatter(const int* __restrict__ ei, int E) {
    int e = blockIdx.x * blockDim.x + threadIdx.x;
    if (e >= E) return;
    int s = ei[e], d = ei[E + e];
    int pos = atomicAdd(&g_cursor[d], 1);
    g_csrsrc[g_rowptr[d] + pos] = s;
}

// ---------------- SAGE mean gather: warp per node ----------------
__global__ void k_sage_gather(const float* __restrict__ x, int N) {
    int gt = blockIdx.x * blockDim.x + threadIdx.x;
    int n = gt >> 5, lane = gt & 31;
    if (n >= N) return;
    int beg = g_rowptr[n], end = g_rowptr[n + 1];
    float4 acc = make_float4(0.f, 0.f, 0.f, 0.f);
    for (int i = beg; i < end; i++) {
        int s = g_csrsrc[i];
        float4 v = ((const float4*)(x + (size_t)s * DF))[lane];
        acc.x += v.x; acc.y += v.y; acc.z += v.z; acc.w += v.w;
    }
    float inv = 1.f / fmaxf((float)(end - beg), 1.f);
    acc.x *= inv; acc.y *= inv; acc.z *= inv; acc.w *= inv;
    ((float4*)(g_agg + (size_t)n * DF))[lane] = acc;
}

// ---------------- tensor-core GEMM (split-bf16, fp32-accurate) ----------------
// C = A1@B1 (+A2@B2) (+bias) (relu).  Each operand v = hi + lo (bf16 pair);
// product = hi*hi + hi*lo + lo*hi  (error ~2^-17).
#define TBM 128
#define TBN 64
#define TBK 32

__device__ __forceinline__ u32 ld2bf(const __nv_bfloat16* p) {
    return *reinterpret_cast<const u32*>(p);
}

__device__ __forceinline__ void mma_bf16(float* d, const u32* a, u32 b0, u32 b1) {
    asm volatile(
        "mma.sync.aligned.m16n8k16.row.col.f32.bf16.bf16.f32 "
        "{%0,%1,%2,%3},{%4,%5,%6,%7},{%8,%9},{%0,%1,%2,%3};"
        : "+f"(d[0]), "+f"(d[1]), "+f"(d[2]), "+f"(d[3])
        : "r"(a[0]), "r"(a[1]), "r"(a[2]), "r"(a[3]), "r"(b0), "r"(b1));
}

__global__ __launch_bounds__(256) void k_gemm_tc(
    const float* __restrict__ A1, const float* __restrict__ B1,
    const float* __restrict__ A2, const float* __restrict__ B2,
    const float* __restrict__ bias, float* __restrict__ C,
    int M, int K, int Ncols, int do_relu) {
    __shared__ __nv_bfloat16 Ah[TBM][40];
    __shared__ __nv_bfloat16 Al[TBM][40];
    __shared__ __nv_bfloat16 Bh[TBN][40];   // transposed: [n][k]
    __shared__ __nv_bfloat16 Bl[TBN][40];
    int tid = threadIdx.x;
    int w = tid >> 5, lane = tid & 31;
    int wm = w & 3, wn = w >> 2;       // 4 x 2 warp grid; warp tile 32x32
    int m0 = blockIdx.x * TBM, n0 = blockIdx.y * TBN;
    float acc[2][4][4] = {};
    int npairs = A2 ? 2 : 1;

    for (int p = 0; p < npairs; p++) {
        const float* A = p ? A2 : A1;
        const float* B = p ? B2 : B1;
        for (int k0 = 0; k0 < K; k0 += TBK) {
            __syncthreads();
            // stage A tile 128x32 (fp32 -> hi/lo bf16)
            #pragma unroll
            for (int i = 0; i < 4; i++) {
                int fid = tid * 4 + i;
                int row = fid >> 3;
                int c4 = (fid & 7) * 4;
                float4 v = make_float4(0.f, 0.f, 0.f, 0.f);
                if (m0 + row < M)
                    v = *(const float4*)(A + (size_t)(m0 + row) * K + k0 + c4);
                float vv[4] = {v.x, v.y, v.z, v.w};
                #pragma unroll
                for (int j = 0; j < 4; j++) {
                    __nv_bfloat16 hi = __float2bfloat16(vv[j]);
                    float rem = vv[j] - __bfloat162float(hi);
                    Ah[row][c4 + j] = hi;
                    Al[row][c4 + j] = __float2bfloat16(rem);
                }
            }
            // stage B tile 32x64 transposed
            #pragma unroll
            for (int i = 0; i < 2; i++) {
                int fid = tid * 2 + i;
                int kr = fid >> 4;
                int c4 = (fid & 15) * 4;
                float4 v = *(const float4*)(B + (size_t)(k0 + kr) * Ncols + n0 + c4);
                float vv[4] = {v.x, v.y, v.z, v.w};
                #pragma unroll
                for (int j = 0; j < 4; j++) {
                    __nv_bfloat16 hi = __float2bfloat16(vv[j]);
                    float rem = vv[j] - __bfloat162float(hi);
                    Bh[c4 + j][kr] = hi;
                    Bl[c4 + j][kr] = __float2bfloat16(rem);
                }
            }
            __syncthreads();
            #pragma unroll
            for (int kk = 0; kk < TBK; kk += 16) {
                int kc = kk + (lane & 3) * 2;
                u32 bh[4][2];
                u32 bl[4][2];
                #pragma unroll
                for (int nt = 0; nt < 4; nt++) {
                    int nc = wn * 32 + nt * 8 + (lane >> 2);
                    bh[nt][0] = ld2bf(&Bh[nc][kc]);
                    bh[nt][1] = ld2bf(&Bh[nc][kc + 8]);
                    bl[nt][0] = ld2bf(&Bl[nc][kc]);
                    bl[nt][1] = ld2bf(&Bl[nc][kc + 8]);
                }
                #pragma unroll
                for (int mt = 0; mt < 2; mt++) {
                    int ar = wm * 32 + mt * 16 + (lane >> 2);
                    int ar8 = ar + 8;
                    int kc8 = kc + 8;
                    u32 ah[4];
                    u32 al[4];
                    ah[0] = ld2bf(&Ah[ar][kc]);
                    ah[1] = ld2bf(&Ah[ar8][kc]);
                    ah[2] = ld2bf(&Ah[ar][kc8]);
                    ah[3] = ld2bf(&Ah[ar8][kc8]);
                    al[0] = ld2bf(&Al[ar][kc]);
                    al[1] = ld2bf(&Al[ar8][kc]);
                    al[2] = ld2bf(&Al[ar][kc8]);
                    al[3] = ld2bf(&Al[ar8][kc8]);
                    #pragma unroll
                    for (int nt = 0; nt < 4; nt++) {
                        mma_bf16(acc[mt][nt], ah, bh[nt][0], bh[nt][1]);
                        mma_bf16(acc[mt][nt], ah, bl[nt][0], bl[nt][1]);
                        mma_bf16(acc[mt][nt], al, bh[nt][0], bh[nt][1]);
                    }
                }
            }
        }
    }
    // epilogue
    #pragma unroll
    for (int mt = 0; mt < 2; mt++) {
        int r0 = m0 + wm * 32 + mt * 16 + (lane >> 2);
        #pragma unroll
        for (int nt = 0; nt < 4; nt++) {
            int c0 = n0 + wn * 32 + nt * 8 + (lane & 3) * 2;
            float2 v0 = make_float2(acc[mt][nt][0], acc[mt][nt][1]);
            float2 v1 = make_float2(acc[mt][nt][2], acc[mt][nt][3]);
            if (bias) {
                float2 bb = *(const float2*)(bias + c0);
                v0.x += bb.x; v0.y += bb.y;
                v1.x += bb.x; v1.y += bb.y;
            }
            if (do_relu) {
                v0.x = fmaxf(v0.x, 0.f); v0.y = fmaxf(v0.y, 0.f);
                v1.x = fmaxf(v1.x, 0.f); v1.y = fmaxf(v1.y, 0.f);
            }
            if (r0 < M) *(float2*)(C + (size_t)r0 * Ncols + c0) = v0;
            if (r0 + 8 < M) *(float2*)(C + (size_t)(r0 + 8) * Ncols + c0) = v1;
        }
    }
}

// ---------------- attention-vector precompute ----------------
__global__ void k_att_vec(const float* __restrict__ Wsrc, const float* __restrict__ Wdst,
                          const float* __restrict__ atts, const float* __restrict__ attd) {
    int t = blockIdx.x * blockDim.x + threadIdx.x;
    if (t >= DF * HEADS) return;
    int k = t >> 2, h = t & 3;
    float s = 0.f, d = 0.f;
    for (int c = 0; c < DF; c++) {
        s = fmaf(Wsrc[(size_t)k * 512 + h * 128 + c], atts[h * 128 + c], s);
        d = fmaf(Wdst[(size_t)k * 512 + h * 128 + c], attd[h * 128 + c], d);
    }
    g_vs[k * 4 + h] = s;
    g_vd[k * 4 + h] = d;
}

// rearranged stacked GAT weight: Bstack[h*128+k][c] = 0.25 * W_src[k][h*128+c]
__global__ void k_bstack(const float* __restrict__ Wsrc) {
    int t = blockIdx.x * blockDim.x + threadIdx.x;
    if (t >= 512 * 128) return;
    int j = t >> 7, c = t & 127;
    int h = j >> 7, k = j & 127;
    g_bstack[t] = 0.25f * Wsrc[(size_t)k * 512 + h * 128 + c];
}

// ---------------- per-node a_s, a_d: warp per node ----------------
__global__ void k_asd(int N) {
    __shared__ float svs[DF * 4];
    __shared__ float svd[DF * 4];
    for (int i = threadIdx.x; i < DF * 4; i += blockDim.x) {
        svs[i] = g_vs[i];
        svd[i] = g_vd[i];
    }
    __syncthreads();
    int gt = blockIdx.x * blockDim.x + threadIdx.x;
    int n = gt >> 5, lane = gt & 31;
    if (n >= N) return;
    float as[4] = {}, ad[4] = {};
    #pragma unroll
    for (int kk = 0; kk < 4; kk++) {
        int k = lane + kk * 32;
        float hv = g_h[(size_t)n * DF + k];
        #pragma unroll
        for (int h = 0; h < 4; h++) {
            as[h] = fmaf(hv, svs[k * 4 + h], as[h]);
            ad[h] = fmaf(hv, svd[k * 4 + h], ad[h]);
        }
    }
    #pragma unroll
    for (int h = 0; h < 4; h++) {
        #pragma unroll
        for (int off = 16; off > 0; off >>= 1) {
            as[h] += __shfl_down_sync(0xffffffff, as[h], off);
            ad[h] += __shfl_down_sync(0xffffffff, ad[h], off);
        }
    }
    if (lane == 0) {
        #pragma unroll
        for (int h = 0; h < 4; h++) {
            g_as[n * 4 + h] = as[h];
            g_ad[n * 4 + h] = ad[h];
        }
    }
}

// ---------------- fused GAT softmax + aggregation: warp per node ----------------
__global__ void k_gat_gather(int N) {
    int gt = blockIdx.x * blockDim.x + threadIdx.x;
    int n = gt >> 5, lane = gt & 31;
    if (n >= N) return;
    int beg = g_rowptr[n], end = g_rowptr[n + 1];
    float4 ad = *(const float4*)(g_ad + (size_t)n * 4);

    float4 m = make_float4(-INFINITY, -INFINITY, -INFINITY, -INFINITY);
    for (int i = beg + lane; i < end; i += 32) {
        int s = g_csrsrc[i];
        float4 as = *(const float4*)(g_as + (size_t)s * 4);
        m.x = fmaxf(m.x, lrelu(as.x + ad.x));
        m.y = fmaxf(m.y, lrelu(as.y + ad.y));
        m.z = fmaxf(m.z, lrelu(as.z + ad.z));
        m.w = fmaxf(m.w, lrelu(as.w + ad.w));
    }
    #pragma unroll
    for (int o = 16; o > 0; o >>= 1) {
        m.x = fmaxf(m.x, __shfl_xor_sync(0xffffffff, m.x, o));
        m.y = fmaxf(m.y, __shfl_xor_sync(0xffffffff, m.y, o));
        m.z = fmaxf(m.z, __shfl_xor_sync(0xffffffff, m.z, o));
        m.w = fmaxf(m.w, __shfl_xor_sync(0xffffffff, m.w, o));
    }

    float4 den = make_float4(0.f, 0.f, 0.f, 0.f);
    float4 a0 = make_float4(0.f, 0.f, 0.f, 0.f);
    float4 a1 = a0, a2 = a0, a3 = a0;
    for (int i = beg; i < end; i++) {
        int s = g_csrsrc[i];
        float4 as = *(const float4*)(g_as + (size_t)s * 4);
        float4 w;
        w.x = __expf(lrelu(as.x + ad.x) - m.x);
        w.y = __expf(lrelu(as.y + ad.y) - m.y);
        w.z = __expf(lrelu(as.z + ad.z) - m.z);
        w.w = __expf(lrelu(as.w + ad.w) - m.w);
        den.x += w.x; den.y += w.y; den.z += w.z; den.w += w.w;
        float4 hv = ((const float4*)(g_h + (size_t)s * DF))[lane];
        a0.x = fmaf(hv.x, w.x, a0.x); a0.y = fmaf(hv.y, w.x, a0.y);
        a0.z = fmaf(hv.z, w.x, a0.z); a0.w = fmaf(hv.w, w.x, a0.w);
        a1.x = fmaf(hv.x, w.y, a1.x); a1.y = fmaf(hv.y, w.y, a1.y);
        a1.z = fmaf(hv.z, w.y, a1.z); a1.w = fmaf(hv.w, w.y, a1.w);
        a2.x = fmaf(hv.x, w.z, a2.x); a2.y = fmaf(hv.y, w.z, a2.y);
        a2.z = fmaf(hv.z, w.z, a2.z); a2.w = fmaf(hv.w, w.z, a2.w);
        a3.x = fmaf(hv.x, w.w, a3.x); a3.y = fmaf(hv.y, w.w, a3.y);
        a3.z = fmaf(hv.z, w.w, a3.z); a3.w = fmaf(hv.w, w.w, a3.w);
    }
    float i0 = den.x > 0.f ? 1.f / den.x : 0.f;
    float i1 = den.y > 0.f ? 1.f / den.y : 0.f;
    float i2 = den.z > 0.f ? 1.f / den.z : 0.f;
    float i3 = den.w > 0.f ? 1.f / den.w : 0.f;
    float4* outp = (float4*)(g_aggh + (size_t)n * 512);
    a0.x *= i0; a0.y *= i0; a0.z *= i0; a0.w *= i0;
    a1.x *= i1; a1.y *= i1; a1.z *= i1; a1.w *= i1;
    a2.x *= i2; a2.y *= i2; a2.z *= i2; a2.w *= i2;
    a3.x *= i3; a3.y *= i3; a3.z *= i3; a3.w *= i3;
    outp[0 * 32 + lane] = a0;
    outp[1 * 32 + lane] = a1;
    outp[2 * 32 + lane] = a2;
    outp[3 * 32 + lane] = a3;
}

// ---------------- launch ----------------
extern "C" void kernel_launch(void* const* d_in, const int* in_sizes, int n_in,
                              void* d_out, int out_size) {
    const float* x      = (const float*)d_in[0];
    const int*   ei     = (const int*)d_in[1];
    const float* W_l    = (const float*)d_in[2];
    const float* W_r    = (const float*)d_in[3];
    const float* b_sage = (const float*)d_in[4];
    const float* W_src  = (const float*)d_in[5];
    const float* W_dst  = (const float*)d_in[6];
    const float* att_s  = (const float*)d_in[7];
    const float* att_d  = (const float*)d_in[8];
    const float* b_gat  = (const float*)d_in[9];
    const float* W_lin  = (const float*)d_in[10];
    const float* b_lin  = (const float*)d_in[11];
    float* out = (float*)d_out;

    int N = in_sizes[0] / DF;
    int E = in_sizes[1] / 2;

    float *p_agg, *p_h, *p_aggh, *p_bstack;
    int* p_deg;
    cudaGetSymbolAddress((void**)&p_agg, g_agg);
    cudaGetSymbolAddress((void**)&p_h, g_h);
    cudaGetSymbolAddress((void**)&p_aggh, g_aggh);
    cudaGetSymbolAddress((void**)&p_bstack, g_bstack);
    cudaGetSymbolAddress((void**)&p_deg, g_deg);

    const int T = 256;
    int edgeBlocks = (E + T - 1) / T;
    int nodeWarpBlocks = (N * 32 + T - 1) / T;

    // ---- CSR build ----
    k_zero_int<<<(N + T - 1) / T, T>>>(p_deg, N);
    k_count<<<edgeBlocks, T>>>(ei, E);
    k_scan<<<1, 1024>>>(N);
    k_csr_scatter<<<edgeBlocks, T>>>(ei, E);

    // ---- small precomputes ----
    k_att_vec<<<2, T>>>(W_src, W_dst, att_s, att_d);
    k_bstack<<<(512 * 128 + T - 1) / T, T>>>(W_src);

    // ---- SAGE ----
    k_sage_gather<<<nodeWarpBlocks, T>>>(x, N);
    dim3 g1((N + TBM - 1) / TBM, DF / TBN);
    k_gemm_tc<<<g1, 256>>>(p_agg, W_l, x, W_r, b_sage, p_h, N, 128, DF, 1);

    // ---- GAT ----
    k_asd<<<nodeWarpBlocks, T>>>(N);
    k_gat_gather<<<nodeWarpBlocks, T>>>(N);
    k_gemm_tc<<<g1, 256>>>(p_aggh, p_bstack, nullptr, nullptr, b_gat, p_agg, N, 512, DF, 1);

    // ---- final linear ----
    dim3 g3((N + TBM - 1) / TBM, 64 / TBN);
    k_gemm_tc<<<g3, 256>>>(p_agg, W_lin, nullptr, nullptr, b_lin, out, N, 128, 64, 0);
}